// round 15
// baseline (speedup 1.0000x reference)
#include <cuda_runtime.h>
#include <cstdint>

#define TSTEPS 256
#define HSZ 50
#define ISZ 7
#define EPB 32
#define NTH 512
#define NBLK 128
#define MW 14          // MMA warps; pair wp=w>>1 owns cells wp*8..+7, half=w&1 owns n-chunks
#define K0C 8          // layer0 K chunks (cols 0..63: 50 h0 + 7 x + pad)
#define K1C 14         // layer1 K chunks (cols 0..111: 50 h0 + pad + h1 ping/pong)
#define SW 116         // W1 row stride (224 rows)
#define SA 68          // A0 row stride (224 rows, 64 cols used)
#define S0 68          // T0 row stride (32 rows, double buffered)
#define S1 172         // T1 row stride (32 rows; h0 @0-49, h1 @56-105 / 112-161)

// smem float offsets
#define OFF_W1 0                   // [224][116] = 25984
#define OFF_A0 25984               // [224][68]  = 15232
#define OFF_T0 41216               // [2][32][68] = 4352
#define OFF_T1 45568               // [32][172]   = 5504
#define SMEMF  51072               // 204288 bytes

__device__ __forceinline__ float sigm(float v) {
    return __fdividef(1.f, 1.f + __expf(-v));
}
__device__ __forceinline__ float tanh_f(float v) {
    return __fdividef(2.f, 1.f + __expf(-2.f * v)) - 1.f;
}
__device__ __forceinline__ uint32_t tf32u(float f) {
    uint32_t u; asm("cvt.rna.tf32.f32 %0, %1;" : "=r"(u) : "f"(f)); return u;
}
__device__ __forceinline__ float tf32f(float f) {
    return __uint_as_float(tf32u(f));
}
__device__ __forceinline__ void mma_tf32(float d[4], const uint32_t a[4],
                                         uint32_t b0, uint32_t b1) {
    asm volatile(
        "mma.sync.aligned.m16n8k8.row.col.f32.tf32.tf32.f32 "
        "{%0,%1,%2,%3}, {%4,%5,%6,%7}, {%8,%9}, {%0,%1,%2,%3};"
        : "+f"(d[0]), "+f"(d[1]), "+f"(d[2]), "+f"(d[3])
        : "r"(a[0]), "r"(a[1]), "r"(a[2]), "r"(a[3]), "r"(b0), "r"(b1));
}

// layer0 weight element for (cell j, gate gi, col c over [h0(50) | x(7) | 0])
__device__ __forceinline__ float w0v(const float* __restrict__ wih0,
                                     const float* __restrict__ whh0,
                                     int j, int gi, int c) {
    if (j >= HSZ) return 0.f;
    if (c < 50) return whh0[(gi * HSZ + j) * HSZ + c];
    if (c < 57) return wih0[(gi * HSZ + j) * ISZ + (c - 50)];
    return 0.f;
}

// load a 4-reg A fragment from permuted smem matrix (rows r, r+8; cols c, c+4)
__device__ __forceinline__ void ldfragA(uint32_t a[4], const float* __restrict__ base,
                                        int r, int stride, int c) {
    const float* ap = base + r * stride + c;
    a[0] = __float_as_uint(ap[0]);
    a[1] = __float_as_uint(ap[8 * stride]);
    a[2] = __float_as_uint(ap[4]);
    a[3] = __float_as_uint(ap[8 * stride + 4]);
}

__global__ __launch_bounds__(NTH, 1)
void lstm2_tc_v9(const float* __restrict__ x,
                 const float* __restrict__ w_ih0, const float* __restrict__ w_hh0,
                 const float* __restrict__ b_ih0, const float* __restrict__ b_hh0,
                 const float* __restrict__ w_ih1, const float* __restrict__ w_hh1,
                 const float* __restrict__ b_ih1, const float* __restrict__ b_hh1,
                 const float* __restrict__ w_fc,  const float* __restrict__ b_fc,
                 float* __restrict__ out)
{
    extern __shared__ float sm[];
    const int tid  = threadIdx.x;
    const int blk  = blockIdx.x;
    const int wid  = tid >> 5;
    const int lane = tid & 31;
    const int gid  = lane >> 2;      // 0..7
    const int t4   = lane & 3;       // 0..3
    const int wp   = wid >> 1;       // warp pair 0..6
    const int half = wid & 1;        // batch half
    const int nb   = half * 2;       // first n-chunk of this warp
    const int j    = wp * 8 + gid;   // this lane's cell (valid < 50)
    const bool mma_w = (wid < MW);
    const bool jok = (j < HSZ);

    // ---- stage layer1 weights, permuted rows: r = w*32 + tile*16 + hg*8 + g
    //      cell = w*8+g, gate = tile*2+hg; cols: ih1 @0-49, pad 50-55, hh1 @56-105 ----
    for (int i = tid; i < 224 * SW; i += NTH) {
        const int r = i / SW, c = i % SW;
        const int w = r >> 5, rem = r & 31;
        const int tile = rem >> 4, hg = (rem >> 3) & 1, g = rem & 7;
        const int cell = w * 8 + g, gate = tile * 2 + hg;
        float v = 0.f;
        if (cell < HSZ) {
            if (c < 50)                  v = w_ih1[(gate * HSZ + cell) * HSZ + c];
            else if (c >= 56 && c < 106) v = w_hh1[(gate * HSZ + cell) * HSZ + (c - 56)];
        }
        sm[OFF_W1 + i] = tf32f(v);
    }
    // ---- stage layer0 A, same row permutation, cols 0..63 = [h0(50)|x(7)|pad] ----
    for (int i = tid; i < 224 * 64; i += NTH) {
        const int r = i >> 6, c = i & 63;
        const int w = r >> 5, rem = r & 31;
        const int tile = rem >> 4, hg = (rem >> 3) & 1, g = rem & 7;
        const int cell = w * 8 + g, gate = tile * 2 + hg;
        sm[OFF_A0 + r * SA + c] = tf32f(w0v(w_ih0, w_hh0, cell, gate, c));
    }
    // zero operand buffers
    for (int i = tid; i < 2 * 32 * S0; i += NTH) sm[OFF_T0 + i] = 0.f;
    for (int i = tid; i < 32 * S1; i += NTH) sm[OFF_T1 + i] = 0.f;
    __syncthreads();
    // x(t=0) into T0 buf0 cols 50..56
    if (tid < 224) {
        const int e = tid / 7, kx = tid % 7;
        sm[OFF_T0 + e * S0 + 50 + kx] =
            tf32f(x[(size_t)(blk * EPB + e) * (TSTEPS * ISZ) + kx]);
    }

    // per-lane biases (i,f,g,o of cell j); duplicated across the warp pair
    float bi0 = 0.f, bf0 = 0.f, bg0 = 0.f, bo0 = 0.f;
    float bi1 = 0.f, bf1 = 0.f, bg1 = 0.f, bo1 = 0.f;
    if (mma_w && jok) {
        bi0 = b_ih0[0 * HSZ + j] + b_hh0[0 * HSZ + j];
        bf0 = b_ih0[1 * HSZ + j] + b_hh0[1 * HSZ + j];
        bg0 = b_ih0[2 * HSZ + j] + b_hh0[2 * HSZ + j];
        bo0 = b_ih0[3 * HSZ + j] + b_hh0[3 * HSZ + j];
        bi1 = b_ih1[0 * HSZ + j] + b_hh1[0 * HSZ + j];
        bf1 = b_ih1[1 * HSZ + j] + b_hh1[1 * HSZ + j];
        bg1 = b_ih1[2 * HSZ + j] + b_hh1[2 * HSZ + j];
        bo1 = b_ih1[3 * HSZ + j] + b_hh1[3 * HSZ + j];
    }

    const float* xp = x;
    if (tid < 224)
        xp = x + (size_t)(blk * EPB + tid / 7) * (TSTEPS * ISZ) + (tid % 7);

    float c0s[4] = {0.f, 0.f, 0.f, 0.f};
    float c1s[4] = {0.f, 0.f, 0.f, 0.f};

    __syncthreads();

    int buf = 0;
    for (int t = 0; t < TSTEPS; t++) {
        float xv = 0.f;
        if (tid < 224 && t + 1 < TSTEPS) xv = xp[(t + 1) * ISZ];

        const int RB = (t & 1) ? 112 : 56;   // h1 read base this step
        const int WB = (t & 1) ? 56 : 112;   // h1 write base this step
        const float* T0r = sm + OFF_T0 + buf * (32 * S0);
        float* T0w = sm + OFF_T0 + (buf ^ 1) * (32 * S0);

        // ======== P1: layer0 MMA + in-lane activation (this warp's 2 n-chunks) ========
        if (mma_w) {
            float accA[2][4], accB[2][4];
            #pragma unroll
            for (int q = 0; q < 2; q++) {
                accA[q][0] = bi0; accA[q][1] = bi0; accA[q][2] = bf0; accA[q][3] = bf0;
                accB[q][0] = bg0; accB[q][1] = bg0; accB[q][2] = bo0; accB[q][3] = bo0;
            }
            const int rA0 = wp * 32 + gid;         // tileA rows (i,f)
            const int rB0 = wp * 32 + 16 + gid;    // tileB rows (g,o)
            #pragma unroll
            for (int kc = 0; kc < K0C; kc++) {
                const int c = kc * 8 + t4;
                uint32_t aA[4], aB[4];
                ldfragA(aA, sm + OFF_A0, rA0, SA, c);
                ldfragA(aB, sm + OFF_A0, rB0, SA, c);
                #pragma unroll
                for (int q = 0; q < 2; q++) {
                    const float* bp = T0r + ((nb + q) * 8 + gid) * S0 + c;
                    const uint32_t b0 = __float_as_uint(bp[0]);
                    const uint32_t b1 = __float_as_uint(bp[4]);
                    mma_tf32(accA[q], aA, b0, b1);
                    mma_tf32(accB[q], aB, b0, b1);
                }
            }
            #pragma unroll
            for (int q = 0; q < 2; q++) {
                #pragma unroll
                for (int p = 0; p < 2; p++) {
                    const int e = (nb + q) * 8 + t4 * 2 + p;
                    const int idx = q * 2 + p;
                    const float iv = accA[q][p], fv = accA[q][2 + p];
                    const float gv = accB[q][p], ov = accB[q][2 + p];
                    c0s[idx] = sigm(fv) * c0s[idx] + sigm(iv) * tanh_f(gv);
                    const float h0 = sigm(ov) * tanh_f(c0s[idx]);
                    if (jok) {
                        const float ht = tf32f(h0);
                        T0w[e * S0 + j] = ht;             // layer0 h for t+1
                        sm[OFF_T1 + e * S1 + j] = ht;     // layer1 input (cols 0-49)
                    }
                }
            }
        }
        __syncthreads();   // barA: h0 + T1 inputs visible

        // x_{t+1} into the other T0 buffer (no reader of T0 in P2)
        if (tid < 224) T0w[(tid / 7) * S0 + 50 + tid % 7] = tf32f(xv);

        // ======== P2: layer1 MMA + in-lane activation ========
        if (mma_w) {
            float accA[2][4], accB[2][4];
            #pragma unroll
            for (int q = 0; q < 2; q++) {
                accA[q][0] = bi1; accA[q][1] = bi1; accA[q][2] = bf1; accA[q][3] = bf1;
                accB[q][0] = bg1; accB[q][1] = bg1; accB[q][2] = bo1; accB[q][3] = bo1;
            }
            const int rA1 = wp * 32 + gid;
            const int rB1 = wp * 32 + 16 + gid;
            #pragma unroll
            for (int kc = 0; kc < K1C; kc++) {
                const int acol = kc * 8 + t4;
                const int bcol = (kc < 7) ? acol : (RB + (kc - 7) * 8 + t4);
                uint32_t aA[4], aB[4];
                ldfragA(aA, sm + OFF_W1, rA1, SW, acol);
                ldfragA(aB, sm + OFF_W1, rB1, SW, acol);
                #pragma unroll
                for (int q = 0; q < 2; q++) {
                    const float* bp = sm + OFF_T1 + ((nb + q) * 8 + gid) * S1 + bcol;
                    const uint32_t b0 = __float_as_uint(bp[0]);
                    const uint32_t b1 = __float_as_uint(bp[4]);
                    mma_tf32(accA[q], aA, b0, b1);
                    mma_tf32(accB[q], aB, b0, b1);
                }
            }
            #pragma unroll
            for (int q = 0; q < 2; q++) {
                #pragma unroll
                for (int p = 0; p < 2; p++) {
                    const int e = (nb + q) * 8 + t4 * 2 + p;
                    const int idx = q * 2 + p;
                    const float iv = accA[q][p], fv = accA[q][2 + p];
                    const float gv = accB[q][p], ov = accB[q][2 + p];
                    c1s[idx] = sigm(fv) * c1s[idx] + sigm(iv) * tanh_f(gv);
                    const float h1 = sigm(ov) * tanh_f(c1s[idx]);
                    if (jok) sm[OFF_T1 + e * S1 + WB + j] = tf32f(h1);
                }
            }
        }
        __syncthreads();   // barB: h1(WB) + x visible for next step
        buf ^= 1;
    }

    // ---- FC head: final h1 at cols 56..105 (t=255 wrote WB=56) ----
    if (tid < 224) {
        const int i = tid % 7, e = tid / 7;
        float s = b_fc[i];
        #pragma unroll 10
        for (int k = 0; k < HSZ; k++)
            s = fmaf(w_fc[i * HSZ + k], sm[OFF_T1 + e * S1 + 56 + k], s);
        out[(size_t)(blk * EPB + e) * ISZ + i] = s;
    }
}

extern "C" void kernel_launch(void* const* d_in, const int* in_sizes, int n_in,
                              void* d_out, int out_size)
{
    const float* x     = (const float*)d_in[0];
    const float* w_ih0 = (const float*)d_in[1];
    const float* w_hh0 = (const float*)d_in[2];
    const float* b_ih0 = (const float*)d_in[3];
    const float* b_hh0 = (const float*)d_in[4];
    const float* w_ih1 = (const float*)d_in[5];
    const float* w_hh1 = (const float*)d_in[6];
    const float* b_ih1 = (const float*)d_in[7];
    const float* b_hh1 = (const float*)d_in[8];
    const float* w_fc  = (const float*)d_in[9];
    const float* b_fc  = (const float*)d_in[10];
    float* out = (float*)d_out;

    const size_t smem_bytes = SMEMF * sizeof(float);
    cudaFuncSetAttribute(lstm2_tc_v9,
                         cudaFuncAttributeMaxDynamicSharedMemorySize,
                         (int)smem_bytes);

    lstm2_tc_v9<<<NBLK, NTH, smem_bytes>>>(
        x, w_ih0, w_hh0, b_ih0, b_hh0,
        w_ih1, w_hh1, b_ih1, b_hh1,
        w_fc, b_fc, out);
}

// round 16
// speedup vs baseline: 1.2388x; 1.2388x over previous
#include <cuda_runtime.h>
#include <cstdint>

#define TSTEPS 256
#define HSZ 50
#define ISZ 7
#define EPB 32
#define NTH 512
#define NBLK 128
#define MW 7           // MMA warps; warp w owns M-tiles w and w+7 (latter if w<6)
#define K0C 8          // layer0 K chunks (K=64: 50 h + 7 x + 7 zero)
#define K1C 13         // layer1 K chunks (K=104: 50 h0 + 50 h1 + 4 zero)
#define SG 36          // gates buffer row stride
#define S0 68          // hT0 row stride (32 rows x 68)
#define S1 108         // hT1 / Wsm1 row stride
#define SA 68          // A0 smem tile stride

// smem float offsets
#define OFF_W1 0                   // [208][108] = 22464
#define OFF_G  22464               // [208][36]  = 7488
#define OFF_T0 29952               // [32][68]   = 2176
#define OFF_T1 32128               // [32][108]  = 3456
#define OFF_B0 35584               // [208]
#define OFF_B1 35792               // [208]
#define OFF_A0 36000               // [96][68]   = 6528 (layer0 A rows 112..207)
#define SMEMF  42528               // 170112 bytes

// HW tanh (sm_75+ MUFU.TANH): 1 MUFU op, ~2^-11 abs err
__device__ __forceinline__ float tanh_hw(float v) {
    float r; asm("tanh.approx.f32 %0, %1;" : "=f"(r) : "f"(v)); return r;
}
__device__ __forceinline__ float sigm(float v) {
    return fmaf(tanh_hw(0.5f * v), 0.5f, 0.5f);
}
__device__ __forceinline__ float tanh_f(float v) {
    return tanh_hw(v);
}
__device__ __forceinline__ uint32_t tf32u(float f) {
    uint32_t u; asm("cvt.rna.tf32.f32 %0, %1;" : "=r"(u) : "f"(f)); return u;
}
__device__ __forceinline__ float tf32f(float f) {
    return __uint_as_float(tf32u(f));
}
__device__ __forceinline__ void mma_tf32(float d[4], const uint32_t a[4],
                                         uint32_t b0, uint32_t b1) {
    asm volatile(
        "mma.sync.aligned.m16n8k8.row.col.f32.tf32.tf32.f32 "
        "{%0,%1,%2,%3}, {%4,%5,%6,%7}, {%8,%9}, {%0,%1,%2,%3};"
        : "+f"(d[0]), "+f"(d[1]), "+f"(d[2]), "+f"(d[3])
        : "r"(a[0]), "r"(a[1]), "r"(a[2]), "r"(a[3]), "r"(b0), "r"(b1));
}

// layer0 A element (gate-row r in [j][i,f,g,o] order, col c over [h(50)|x(7)|0])
__device__ __forceinline__ float w0val(const float* __restrict__ wih0,
                                       const float* __restrict__ whh0,
                                       int r, int c) {
    if (r >= 200) return 0.f;
    const int j = r >> 2, gi = r & 3;
    if (c < 50) return whh0[(gi * 50 + j) * 50 + c];
    if (c < 57) return wih0[(gi * 50 + j) * 7 + (c - 50)];
    return 0.f;
}

__global__ __launch_bounds__(NTH, 1)
void lstm2_tc_v10(const float* __restrict__ x,
                  const float* __restrict__ w_ih0, const float* __restrict__ w_hh0,
                  const float* __restrict__ b_ih0, const float* __restrict__ b_hh0,
                  const float* __restrict__ w_ih1, const float* __restrict__ w_hh1,
                  const float* __restrict__ b_ih1, const float* __restrict__ b_hh1,
                  const float* __restrict__ w_fc,  const float* __restrict__ b_fc,
                  float* __restrict__ out)
{
    extern __shared__ float sm[];
    const int tid  = threadIdx.x;
    const int blk  = blockIdx.x;
    const int wid  = tid >> 5;
    const int lane = tid & 31;
    const int gid  = lane >> 2;     // groupID 0..7
    const int t4   = lane & 3;      // threadID in group

    // ---- stage layer1 weights [208][104] (tf32) ----
    for (int i = tid; i < 208 * 104; i += NTH) {
        const int r = i / 104, k = i % 104;
        float v = 0.f;
        if (r < 200) {
            const int j = r >> 2, gi = r & 3;
            if (k < 50)       v = w_ih1[(gi * 50 + j) * 50 + k];
            else if (k < 100) v = w_hh1[(gi * 50 + j) * 50 + (k - 50)];
        }
        sm[OFF_W1 + r * S1 + k] = tf32f(v);
    }
    // layer0 A for tiles 7..12 (gate rows 112..207) into smem
    for (int i = tid; i < 96 * 64; i += NTH) {
        const int r = i >> 6, k = i & 63;
        sm[OFF_A0 + r * SA + k] = tf32f(w0val(w_ih0, w_hh0, 112 + r, k));
    }
    // biases (fp32, accumulator init)
    for (int i = tid; i < 208; i += NTH) {
        float v0 = 0.f, v1 = 0.f;
        if (i < 200) {
            const int j = i >> 2, gi = i & 3;
            v0 = b_ih0[gi * 50 + j] + b_hh0[gi * 50 + j];
            v1 = b_ih1[gi * 50 + j] + b_hh1[gi * 50 + j];
        }
        sm[OFF_B0 + i] = v0;
        sm[OFF_B1 + i] = v1;
    }
    // zero operand buffers
    for (int i = tid; i < 32 * S0; i += NTH) sm[OFF_T0 + i] = 0.f;
    for (int i = tid; i < 32 * S1; i += NTH) sm[OFF_T1 + i] = 0.f;
    __syncthreads();
    // x(t=0) into hT0 cols 50..56
    if (tid < 224) {
        const int e = tid / 7, kx = tid % 7;
        sm[OFF_T0 + e * S0 + 50 + kx] =
            tf32f(x[(size_t)(blk * EPB + e) * (TSTEPS * ISZ) + kx]);
    }
    __syncthreads();

    // ---- layer0 A-fragments for tile A (rows wid*16..) resident in registers ----
    const int MA = wid * 16;
    const int MB = (wid + MW) * 16;      // second tile rows (wid<6)
    const bool hasB = (wid < MW - 1);    // warps 0..5 have a second tile
    uint32_t wa0[K0C][4];
    if (wid < MW) {
        const int r0 = MA + gid, r1 = r0 + 8;
        #pragma unroll
        for (int kc = 0; kc < K0C; kc++) {
            const int c0 = kc * 8 + t4, c1 = c0 + 4;
            wa0[kc][0] = tf32u(w0val(w_ih0, w_hh0, r0, c0));
            wa0[kc][1] = tf32u(w0val(w_ih0, w_hh0, r1, c0));
            wa0[kc][2] = tf32u(w0val(w_ih0, w_hh0, r0, c1));
            wa0[kc][3] = tf32u(w0val(w_ih0, w_hh0, r1, c1));
        }
    }

    // activation thread mapping: tid<400 -> (j = tid>>3, g = tid&7) owns elems 4g..4g+3
    const int jj = tid >> 3;
    const int gg = tid & 7;
    float c0s[4] = {0.f, 0.f, 0.f, 0.f};
    float c1s[4] = {0.f, 0.f, 0.f, 0.f};

    const float* xp = x;
    if (tid < 224)
        xp = x + (size_t)(blk * EPB + tid / 7) * (TSTEPS * ISZ) + (tid % 7);

    for (int t = 0; t < TSTEPS; t++) {
        float xv = 0.f;
        if (tid < 224 && t + 1 < TSTEPS) xv = xp[(t + 1) * ISZ];

        // ============ MMA layer 0 (two M-tiles per warp, B loaded once) ============
        if (wid < MW) {
            float accA[4][4], accB[4][4];
            {
                const float al = sm[OFF_B0 + MA + gid];
                const float ah = sm[OFF_B0 + MA + 8 + gid];
                const float bl = hasB ? sm[OFF_B0 + MB + gid] : 0.f;
                const float bh = hasB ? sm[OFF_B0 + MB + 8 + gid] : 0.f;
                #pragma unroll
                for (int n = 0; n < 4; n++) {
                    accA[n][0] = al; accA[n][1] = al; accA[n][2] = ah; accA[n][3] = ah;
                    accB[n][0] = bl; accB[n][1] = bl; accB[n][2] = bh; accB[n][3] = bh;
                }
            }
            #pragma unroll
            for (int kc = 0; kc < K0C; kc++) {
                uint32_t aB[4] = {0u, 0u, 0u, 0u};
                if (hasB) {
                    const float* ap = sm + OFF_A0 + (wid * 16 + gid) * SA + kc * 8 + t4;
                    aB[0] = __float_as_uint(ap[0]);
                    aB[1] = __float_as_uint(ap[8 * SA]);
                    aB[2] = __float_as_uint(ap[4]);
                    aB[3] = __float_as_uint(ap[8 * SA + 4]);
                }
                #pragma unroll
                for (int n = 0; n < 4; n++) {
                    const float* bp = sm + OFF_T0 + (n * 8 + gid) * S0 + kc * 8 + t4;
                    const uint32_t b0 = __float_as_uint(bp[0]);
                    const uint32_t b1 = __float_as_uint(bp[4]);
                    mma_tf32(accA[n], wa0[kc], b0, b1);
                    if (hasB) mma_tf32(accB[n], aB, b0, b1);
                }
            }
            #pragma unroll
            for (int n = 0; n < 4; n++) {
                *reinterpret_cast<float2*>(sm + OFF_G + (MA + gid) * SG + n * 8 + t4 * 2) =
                    make_float2(accA[n][0], accA[n][1]);
                *reinterpret_cast<float2*>(sm + OFF_G + (MA + 8 + gid) * SG + n * 8 + t4 * 2) =
                    make_float2(accA[n][2], accA[n][3]);
                if (hasB) {
                    *reinterpret_cast<float2*>(sm + OFF_G + (MB + gid) * SG + n * 8 + t4 * 2) =
                        make_float2(accB[n][0], accB[n][1]);
                    *reinterpret_cast<float2*>(sm + OFF_G + (MB + 8 + gid) * SG + n * 8 + t4 * 2) =
                        make_float2(accB[n][2], accB[n][3]);
                }
            }
        }
        __syncthreads();

        // ============ activation layer 0 ============
        if (tid < 400) {
            const float* gb = sm + OFF_G + (jj * 4) * SG + gg * 4;
            const float4 vi = *reinterpret_cast<const float4*>(gb);
            const float4 vf = *reinterpret_cast<const float4*>(gb + SG);
            const float4 vg = *reinterpret_cast<const float4*>(gb + 2 * SG);
            const float4 vo = *reinterpret_cast<const float4*>(gb + 3 * SG);
            float hv[4];
            {
                const float* iv = &vi.x; const float* fv = &vf.x;
                const float* gv = &vg.x; const float* ov = &vo.x;
                #pragma unroll
                for (int e = 0; e < 4; e++) {
                    c0s[e] = sigm(fv[e]) * c0s[e] + sigm(iv[e]) * tanh_f(gv[e]);
                    hv[e]  = sigm(ov[e]) * tanh_f(c0s[e]);
                }
            }
            #pragma unroll
            for (int e = 0; e < 4; e++) {
                const float ht = tf32f(hv[e]);
                sm[OFF_T0 + (gg * 4 + e) * S0 + jj] = ht;   // layer0 h for t+1
                sm[OFF_T1 + (gg * 4 + e) * S1 + jj] = ht;   // layer1 input rows 0-49
            }
        }
        if (tid < 224) sm[OFF_T0 + (tid / 7) * S0 + 50 + tid % 7] = tf32f(xv);
        __syncthreads();

        // ============ MMA layer 1 (two M-tiles per warp, B loaded once) ============
        if (wid < MW) {
            float accA[4][4], accB[4][4];
            {
                const float al = sm[OFF_B1 + MA + gid];
                const float ah = sm[OFF_B1 + MA + 8 + gid];
                const float bl = hasB ? sm[OFF_B1 + MB + gid] : 0.f;
                const float bh = hasB ? sm[OFF_B1 + MB + 8 + gid] : 0.f;
                #pragma unroll
                for (int n = 0; n < 4; n++) {
                    accA[n][0] = al; accA[n][1] = al; accA[n][2] = ah; accA[n][3] = ah;
                    accB[n][0] = bl; accB[n][1] = bl; accB[n][2] = bh; accB[n][3] = bh;
                }
            }
            #pragma unroll
            for (int kc = 0; kc < K1C; kc++) {
                uint32_t aA[4], aB[4] = {0u, 0u, 0u, 0u};
                {
                    const float* ap = sm + OFF_W1 + (MA + gid) * S1 + kc * 8 + t4;
                    aA[0] = __float_as_uint(ap[0]);
                    aA[1] = __float_as_uint(ap[8 * S1]);
                    aA[2] = __float_as_uint(ap[4]);
                    aA[3] = __float_as_uint(ap[8 * S1 + 4]);
                }
                if (hasB) {
                    const float* ap = sm + OFF_W1 + (MB + gid) * S1 + kc * 8 + t4;
                    aB[0] = __float_as_uint(ap[0]);
                    aB[1] = __float_as_uint(ap[8 * S1]);
                    aB[2] = __float_as_uint(ap[4]);
                    aB[3] = __float_as_uint(ap[8 * S1 + 4]);
                }
                #pragma unroll
                for (int n = 0; n < 4; n++) {
                    const float* bp = sm + OFF_T1 + (n * 8 + gid) * S1 + kc * 8 + t4;
                    const uint32_t b0 = __float_as_uint(bp[0]);
                    const uint32_t b1 = __float_as_uint(bp[4]);
                    mma_tf32(accA[n], aA, b0, b1);
                    if (hasB) mma_tf32(accB[n], aB, b0, b1);
                }
            }
            #pragma unroll
            for (int n = 0; n < 4; n++) {
                *reinterpret_cast<float2*>(sm + OFF_G + (MA + gid) * SG + n * 8 + t4 * 2) =
                    make_float2(accA[n][0], accA[n][1]);
                *reinterpret_cast<float2*>(sm + OFF_G + (MA + 8 + gid) * SG + n * 8 + t4 * 2) =
                    make_float2(accA[n][2], accA[n][3]);
                if (hasB) {
                    *reinterpret_cast<float2*>(sm + OFF_G + (MB + gid) * SG + n * 8 + t4 * 2) =
                        make_float2(accB[n][0], accB[n][1]);
                    *reinterpret_cast<float2*>(sm + OFF_G + (MB + 8 + gid) * SG + n * 8 + t4 * 2) =
                        make_float2(accB[n][2], accB[n][3]);
                }
            }
        }
        __syncthreads();

        // ============ activation layer 1 ============
        if (tid < 400) {
            const float* gb = sm + OFF_G + (jj * 4) * SG + gg * 4;
            const float4 vi = *reinterpret_cast<const float4*>(gb);
            const float4 vf = *reinterpret_cast<const float4*>(gb + SG);
            const float4 vg = *reinterpret_cast<const float4*>(gb + 2 * SG);
            const float4 vo = *reinterpret_cast<const float4*>(gb + 3 * SG);
            const float* iv = &vi.x; const float* fv = &vf.x;
            const float* gv = &vg.x; const float* ov = &vo.x;
            #pragma unroll
            for (int e = 0; e < 4; e++) {
                c1s[e] = sigm(fv[e]) * c1s[e] + sigm(iv[e]) * tanh_f(gv[e]);
                const float h1 = sigm(ov[e]) * tanh_f(c1s[e]);
                sm[OFF_T1 + (gg * 4 + e) * S1 + 50 + jj] = tf32f(h1);  // rows 50-99 for t+1
            }
        }
        __syncthreads();
    }

    // ---- FC head: out[e][i] = b_fc[i] + sum_k w_fc[i][k] * h1[e][k] ----
    if (tid < 224) {
        const int i = tid % 7, e = tid / 7;
        float s = b_fc[i];
        #pragma unroll 10
        for (int k = 0; k < HSZ; k++)
            s = fmaf(w_fc[i * 50 + k], sm[OFF_T1 + e * S1 + 50 + k], s);
        out[(size_t)(blk * EPB + e) * ISZ + i] = s;
    }
}

extern "C" void kernel_launch(void* const* d_in, const int* in_sizes, int n_in,
                              void* d_out, int out_size)
{
    const float* x     = (const float*)d_in[0];
    const float* w_ih0 = (const float*)d_in[1];
    const float* w_hh0 = (const float*)d_in[2];
    const float* b_ih0 = (const float*)d_in[3];
    const float* b_hh0 = (const float*)d_in[4];
    const float* w_ih1 = (const float*)d_in[5];
    const float* w_hh1 = (const float*)d_in[6];
    const float* b_ih1 = (const float*)d_in[7];
    const float* b_hh1 = (const float*)d_in[8];
    const float* w_fc  = (const float*)d_in[9];
    const float* b_fc  = (const float*)d_in[10];
    float* out = (float*)d_out;

    const size_t smem_bytes = SMEMF * sizeof(float);
    cudaFuncSetAttribute(lstm2_tc_v10,
                         cudaFuncAttributeMaxDynamicSharedMemorySize,
                         (int)smem_bytes);

    lstm2_tc_v10<<<NBLK, NTH, smem_bytes>>>(
        x, w_ih0, w_hh0, b_ih0, b_hh0,
        w_ih1, w_hh1, b_ih1, b_hh1,
        w_fc, b_fc, out);
}

// round 17
// speedup vs baseline: 1.6772x; 1.3538x over previous
#include <cuda_runtime.h>
#include <cuda_bf16.h>
#include <cstdint>

#define TSTEPS 256
#define HSZ 50
#define ISZ 7
#define EPB 32
#define NTH 512
#define NBLK 128
#define MW 7           // MMA warps; warp w owns M-tiles w and w+7 (latter if w<6)
#define K0C 4          // layer0 K chunks of 16 (cols 0..63: 50 h + 7 x + pad)
#define K1C 7          // layer1 K chunks of 16 (cols 0..111: 50 h0 | pad | 50 h1 | pad)
#define SG 36          // gates buffer row stride (fp32 words)
#define SW1 60         // W1 row stride in 32-bit words (112 bf16 cols used)
#define SA0 36         // A0 row stride in words (64 bf16 cols used)
#define ST0 36         // T0 row stride in words (72 bf16: 50 h0 | 7 x | pad)
#define ST1 84         // T1 row stride in words (168 bf16: 50 h0 | pad | 50 h1 | pad)

// smem 32-bit word offsets
#define OFF_W1 0                    // [208][60]  = 12480
#define OFF_A0 12480                // [96][36]   = 3456
#define OFF_G  15936                // [208][36]  = 7488 (fp32)
#define OFF_T0 23424                // [32][36]   = 1152
#define OFF_T1 24576                // [32][84]   = 2688
#define OFF_B0 27264                // [208] fp32
#define OFF_B1 27472                // [208] fp32
#define SMEMW  27680                // 110720 bytes

typedef uint32_t u32;

// HW tanh (sm_75+ MUFU.TANH): 1 MUFU op, ~2^-11 abs err
__device__ __forceinline__ float tanh_hw(float v) {
    float r; asm("tanh.approx.f32 %0, %1;" : "=f"(r) : "f"(v)); return r;
}
__device__ __forceinline__ float sigm(float v) {
    return fmaf(tanh_hw(0.5f * v), 0.5f, 0.5f);
}
__device__ __forceinline__ float tanh_f(float v) {
    return tanh_hw(v);
}
// pack (lo, hi) floats as bf16x2 in one u32 (lo at low half = lower k index)
__device__ __forceinline__ u32 bfp(float lo, float hi) {
    __nv_bfloat162 p = __floats2bfloat162_rn(lo, hi);
    return *reinterpret_cast<u32*>(&p);
}
__device__ __forceinline__ void mma_bf16(float d[4], const u32 a[4],
                                         u32 b0, u32 b1) {
    asm volatile(
        "mma.sync.aligned.m16n8k16.row.col.f32.bf16.bf16.f32 "
        "{%0,%1,%2,%3}, {%4,%5,%6,%7}, {%8,%9}, {%0,%1,%2,%3};"
        : "+f"(d[0]), "+f"(d[1]), "+f"(d[2]), "+f"(d[3])
        : "r"(a[0]), "r"(a[1]), "r"(a[2]), "r"(a[3]), "r"(b0), "r"(b1));
}

// layer0 A element (gate-row r in [j][i,f,g,o] order, col c over [h(50)|x(7)|0])
__device__ __forceinline__ float w0val(const float* __restrict__ wih0,
                                       const float* __restrict__ whh0,
                                       int r, int c) {
    if (r >= 200) return 0.f;
    const int j = r >> 2, gi = r & 3;
    if (c < 50) return whh0[(gi * 50 + j) * 50 + c];
    if (c < 57) return wih0[(gi * 50 + j) * 7 + (c - 50)];
    return 0.f;
}
// layer1 weight element, col c over [ih1(50) | pad6 | hh1(50) | pad]
__device__ __forceinline__ float w1val(const float* __restrict__ wih1,
                                       const float* __restrict__ whh1,
                                       int r, int c) {
    if (r >= 200) return 0.f;
    const int j = r >> 2, gi = r & 3;
    if (c < 50) return wih1[(gi * 50 + j) * 50 + c];
    if (c >= 56 && c < 106) return whh1[(gi * 50 + j) * 50 + (c - 56)];
    return 0.f;
}

__global__ __launch_bounds__(NTH, 1)
void lstm2_tc_v11(const float* __restrict__ x,
                  const float* __restrict__ w_ih0, const float* __restrict__ w_hh0,
                  const float* __restrict__ b_ih0, const float* __restrict__ b_hh0,
                  const float* __restrict__ w_ih1, const float* __restrict__ w_hh1,
                  const float* __restrict__ b_ih1, const float* __restrict__ b_hh1,
                  const float* __restrict__ w_fc,  const float* __restrict__ b_fc,
                  float* __restrict__ out)
{
    extern __shared__ float sm[];
    u32* usm = reinterpret_cast<u32*>(sm);
    __nv_bfloat16* bsm = reinterpret_cast<__nv_bfloat16*>(sm);
    const int tid  = threadIdx.x;
    const int blk  = blockIdx.x;
    const int wid  = tid >> 5;
    const int lane = tid & 31;
    const int gid  = lane >> 2;     // groupID 0..7
    const int t4   = lane & 3;      // threadID in group

    // ---- stage layer1 weights as packed bf16 pairs [208][SW1 words] ----
    for (int i = tid; i < 208 * 56; i += NTH) {
        const int r = i / 56, w = i % 56;
        usm[OFF_W1 + r * SW1 + w] =
            bfp(w1val(w_ih1, w_hh1, r, 2 * w), w1val(w_ih1, w_hh1, r, 2 * w + 1));
    }
    // ---- stage layer0 A rows 112..207 as bf16 pairs [96][SA0 words] ----
    for (int i = tid; i < 96 * 32; i += NTH) {
        const int r = i >> 5, w = i & 31;
        usm[OFF_A0 + r * SA0 + w] =
            bfp(w0val(w_ih0, w_hh0, 112 + r, 2 * w), w0val(w_ih0, w_hh0, 112 + r, 2 * w + 1));
    }
    // biases (fp32, accumulator init)
    for (int i = tid; i < 208; i += NTH) {
        float v0 = 0.f, v1 = 0.f;
        if (i < 200) {
            const int j = i >> 2, gi = i & 3;
            v0 = b_ih0[gi * 50 + j] + b_hh0[gi * 50 + j];
            v1 = b_ih1[gi * 50 + j] + b_hh1[gi * 50 + j];
        }
        sm[OFF_B0 + i] = v0;
        sm[OFF_B1 + i] = v1;
    }
    // zero operand buffers (full, incl. pads)
    for (int i = tid; i < 32 * ST0; i += NTH) usm[OFF_T0 + i] = 0u;
    for (int i = tid; i < 32 * ST1; i += NTH) usm[OFF_T1 + i] = 0u;
    __syncthreads();
    // x(t=0) into T0 bf16 cols 50..56
    if (tid < 224) {
        const int e = tid / 7, kx = tid % 7;
        bsm[(OFF_T0 + e * ST0) * 2 + 50 + kx] =
            __float2bfloat16(x[(size_t)(blk * EPB + e) * (TSTEPS * ISZ) + kx]);
    }
    __syncthreads();

    // ---- layer0 A-fragments for tile A in registers (bf16 pairs, K0C chunks of 16) ----
    const int MA = wid * 16;
    const int MB = (wid + MW) * 16;      // second tile rows (wid<6)
    const bool hasB = (wid < MW - 1);    // warps 0..5 have a second tile
    u32 wa0[K0C][4];
    if (wid < MW) {
        const int r0 = MA + gid, r1 = r0 + 8;
        #pragma unroll
        for (int kc = 0; kc < K0C; kc++) {
            const int c = kc * 16 + 2 * t4;
            wa0[kc][0] = bfp(w0val(w_ih0, w_hh0, r0, c),     w0val(w_ih0, w_hh0, r0, c + 1));
            wa0[kc][1] = bfp(w0val(w_ih0, w_hh0, r1, c),     w0val(w_ih0, w_hh0, r1, c + 1));
            wa0[kc][2] = bfp(w0val(w_ih0, w_hh0, r0, c + 8), w0val(w_ih0, w_hh0, r0, c + 9));
            wa0[kc][3] = bfp(w0val(w_ih0, w_hh0, r1, c + 8), w0val(w_ih0, w_hh0, r1, c + 9));
        }
    }

    // activation thread mapping: tid<400 -> (j = tid>>3, g = tid&7) owns elems 4g..4g+3
    const int jj = tid >> 3;
    const int gg = tid & 7;
    float c0s[4] = {0.f, 0.f, 0.f, 0.f};
    float c1s[4] = {0.f, 0.f, 0.f, 0.f};

    const float* xp = x;
    if (tid < 224)
        xp = x + (size_t)(blk * EPB + tid / 7) * (TSTEPS * ISZ) + (tid % 7);

    for (int t = 0; t < TSTEPS; t++) {
        float xv = 0.f;
        if (tid < 224 && t + 1 < TSTEPS) xv = xp[(t + 1) * ISZ];

        // ============ MMA layer 0 (two M-tiles per warp, B loaded once) ============
        if (wid < MW) {
            float accA[4][4], accB[4][4];
            {
                const float al = sm[OFF_B0 + MA + gid];
                const float ah = sm[OFF_B0 + MA + 8 + gid];
                const float bl = hasB ? sm[OFF_B0 + MB + gid] : 0.f;
                const float bh = hasB ? sm[OFF_B0 + MB + 8 + gid] : 0.f;
                #pragma unroll
                for (int n = 0; n < 4; n++) {
                    accA[n][0] = al; accA[n][1] = al; accA[n][2] = ah; accA[n][3] = ah;
                    accB[n][0] = bl; accB[n][1] = bl; accB[n][2] = bh; accB[n][3] = bh;
                }
            }
            #pragma unroll
            for (int kc = 0; kc < K0C; kc++) {
                u32 aB[4] = {0u, 0u, 0u, 0u};
                if (hasB) {
                    const u32* ap = usm + OFF_A0 + (wid * 16 + gid) * SA0 + kc * 8 + t4;
                    aB[0] = ap[0];
                    aB[1] = ap[8 * SA0];
                    aB[2] = ap[4];
                    aB[3] = ap[8 * SA0 + 4];
                }
                #pragma unroll
                for (int n = 0; n < 4; n++) {
                    const u32* bp = usm + OFF_T0 + (n * 8 + gid) * ST0 + kc * 8 + t4;
                    const u32 b0 = bp[0];
                    const u32 b1 = bp[4];
                    mma_bf16(accA[n], wa0[kc], b0, b1);
                    if (hasB) mma_bf16(accB[n], aB, b0, b1);
                }
            }
            #pragma unroll
            for (int n = 0; n < 4; n++) {
                *reinterpret_cast<float2*>(sm + OFF_G + (MA + gid) * SG + n * 8 + t4 * 2) =
                    make_float2(accA[n][0], accA[n][1]);
                *reinterpret_cast<float2*>(sm + OFF_G + (MA + 8 + gid) * SG + n * 8 + t4 * 2) =
                    make_float2(accA[n][2], accA[n][3]);
                if (hasB) {
                    *reinterpret_cast<float2*>(sm + OFF_G + (MB + gid) * SG + n * 8 + t4 * 2) =
                        make_float2(accB[n][0], accB[n][1]);
                    *reinterpret_cast<float2*>(sm + OFF_G + (MB + 8 + gid) * SG + n * 8 + t4 * 2) =
                        make_float2(accB[n][2], accB[n][3]);
                }
            }
        }
        __syncthreads();

        // ============ activation layer 0 ============
        if (tid < 400) {
            const float* gb = sm + OFF_G + (jj * 4) * SG + gg * 4;
            const float4 vi = *reinterpret_cast<const float4*>(gb);
            const float4 vf = *reinterpret_cast<const float4*>(gb + SG);
            const float4 vg = *reinterpret_cast<const float4*>(gb + 2 * SG);
            const float4 vo = *reinterpret_cast<const float4*>(gb + 3 * SG);
            float hv[4];
            {
                const float* iv = &vi.x; const float* fv = &vf.x;
                const float* gv = &vg.x; const float* ov = &vo.x;
                #pragma unroll
                for (int e = 0; e < 4; e++) {
                    c0s[e] = sigm(fv[e]) * c0s[e] + sigm(iv[e]) * tanh_f(gv[e]);
                    hv[e]  = sigm(ov[e]) * tanh_f(c0s[e]);
                }
            }
            #pragma unroll
            for (int e = 0; e < 4; e++) {
                const __nv_bfloat16 ht = __float2bfloat16(hv[e]);
                bsm[(OFF_T0 + (gg * 4 + e) * ST0) * 2 + jj] = ht;   // layer0 h for t+1
                bsm[(OFF_T1 + (gg * 4 + e) * ST1) * 2 + jj] = ht;   // layer1 input cols 0-49
            }
        }
        if (tid < 224)
            bsm[(OFF_T0 + (tid / 7) * ST0) * 2 + 50 + tid % 7] = __float2bfloat16(xv);
        __syncthreads();

        // ============ MMA layer 1 (two M-tiles per warp, B loaded once) ============
        if (wid < MW) {
            float accA[4][4], accB[4][4];
            {
                const float al = sm[OFF_B1 + MA + gid];
                const float ah = sm[OFF_B1 + MA + 8 + gid];
                const float bl = hasB ? sm[OFF_B1 + MB + gid] : 0.f;
                const float bh = hasB ? sm[OFF_B1 + MB + 8 + gid] : 0.f;
                #pragma unroll
                for (int n = 0; n < 4; n++) {
                    accA[n][0] = al; accA[n][1] = al; accA[n][2] = ah; accA[n][3] = ah;
                    accB[n][0] = bl; accB[n][1] = bl; accB[n][2] = bh; accB[n][3] = bh;
                }
            }
            #pragma unroll
            for (int kc = 0; kc < K1C; kc++) {
                u32 aA[4], aB[4] = {0u, 0u, 0u, 0u};
                {
                    const u32* ap = usm + OFF_W1 + (MA + gid) * SW1 + kc * 8 + t4;
                    aA[0] = ap[0];
                    aA[1] = ap[8 * SW1];
                    aA[2] = ap[4];
                    aA[3] = ap[8 * SW1 + 4];
                }
                if (hasB) {
                    const u32* ap = usm + OFF_W1 + (MB + gid) * SW1 + kc * 8 + t4;
                    aB[0] = ap[0];
                    aB[1] = ap[8 * SW1];
                    aB[2] = ap[4];
                    aB[3] = ap[8 * SW1 + 4];
                }
                #pragma unroll
                for (int n = 0; n < 4; n++) {
                    const u32* bp = usm + OFF_T1 + (n * 8 + gid) * ST1 + kc * 8 + t4;
                    const u32 b0 = bp[0];
                    const u32 b1 = bp[4];
                    mma_bf16(accA[n], aA, b0, b1);
                    if (hasB) mma_bf16(accB[n], aB, b0, b1);
                }
            }
            #pragma unroll
            for (int n = 0; n < 4; n++) {
                *reinterpret_cast<float2*>(sm + OFF_G + (MA + gid) * SG + n * 8 + t4 * 2) =
                    make_float2(accA[n][0], accA[n][1]);
                *reinterpret_cast<float2*>(sm + OFF_G + (MA + 8 + gid) * SG + n * 8 + t4 * 2) =
                    make_float2(accA[n][2], accA[n][3]);
                if (hasB) {
                    *reinterpret_cast<float2*>(sm + OFF_G + (MB + gid) * SG + n * 8 + t4 * 2) =
                        make_float2(accB[n][0], accB[n][1]);
                    *reinterpret_cast<float2*>(sm + OFF_G + (MB + 8 + gid) * SG + n * 8 + t4 * 2) =
                        make_float2(accB[n][2], accB[n][3]);
                }
            }
        }
        __syncthreads();

        // ============ activation layer 1 ============
        if (tid < 400) {
            const float* gb = sm + OFF_G + (jj * 4) * SG + gg * 4;
            const float4 vi = *reinterpret_cast<const float4*>(gb);
            const float4 vf = *reinterpret_cast<const float4*>(gb + SG);
            const float4 vg = *reinterpret_cast<const float4*>(gb + 2 * SG);
            const float4 vo = *reinterpret_cast<const float4*>(gb + 3 * SG);
            const float* iv = &vi.x; const float* fv = &vf.x;
            const float* gv = &vg.x; const float* ov = &vo.x;
            #pragma unroll
            for (int e = 0; e < 4; e++) {
                c1s[e] = sigm(fv[e]) * c1s[e] + sigm(iv[e]) * tanh_f(gv[e]);
                const float h1 = sigm(ov[e]) * tanh_f(c1s[e]);
                bsm[(OFF_T1 + (gg * 4 + e) * ST1) * 2 + 56 + jj] = __float2bfloat16(h1);
            }
        }
        __syncthreads();
    }

    // ---- FC head: out[e][i] = b_fc[i] + sum_k w_fc[i][k] * h1[e][k] ----
    if (tid < 224) {
        const int i = tid % 7, e = tid / 7;
        float s = b_fc[i];
        #pragma unroll 10
        for (int k = 0; k < HSZ; k++)
            s = fmaf(w_fc[i * 50 + k],
                     __bfloat162float(bsm[(OFF_T1 + e * ST1) * 2 + 56 + k]), s);
        out[(size_t)(blk * EPB + e) * ISZ + i] = s;
    }
}

extern "C" void kernel_launch(void* const* d_in, const int* in_sizes, int n_in,
                              void* d_out, int out_size)
{
    const float* x     = (const float*)d_in[0];
    const float* w_ih0 = (const float*)d_in[1];
    const float* w_hh0 = (const float*)d_in[2];
    const float* b_ih0 = (const float*)d_in[3];
    const float* b_hh0 = (const float*)d_in[4];
    const float* w_ih1 = (const float*)d_in[5];
    const float* w_hh1 = (const float*)d_in[6];
    const float* b_ih1 = (const float*)d_in[7];
    const float* b_hh1 = (const float*)d_in[8];
    const float* w_fc  = (const float*)d_in[9];
    const float* b_fc  = (const float*)d_in[10];
    float* out = (float*)d_out;

    const size_t smem_bytes = SMEMW * sizeof(float);
    cudaFuncSetAttribute(lstm2_tc_v11,
                         cudaFuncAttributeMaxDynamicSharedMemorySize,
                         (int)smem_bytes);

    lstm2_tc_v11<<<NBLK, NTH, smem_bytes>>>(
        x, w_ih0, w_hh0, b_ih0, b_hh0,
        w_ih1, w_hh1, b_ih1, b_hh1,
        w_fc, b_fc, out);
}